// round 5
// baseline (speedup 1.0000x reference)
#include <cuda_runtime.h>

#define N_GOAL 16384
#define N_OBS  65536
#define N_TASK 8192
#define NE1    1048576
#define NE2    1048576
#define NB     256
#define FDIM   128
#define SDIM   64

// Scratch (static __device__ arrays — referenced from DEVICE code only!).
__device__ float4 g_YG[N_GOAL * SDIM / 4];  //  4 MB : x_goal @ W1
__device__ float4 g_A [N_OBS  * SDIM / 4];  // 16 MB : x_obs@W1 + b1 + agg
__device__ float4 g_X1[N_OBS  * SDIM / 4];  // 16 MB : after layer 2
__device__ float4 g_G [N_TASK * SDIM / 4];  //  2 MB : x_task + agg2
__device__ int    g_cur1[N_OBS];            // 256 KB : counts/offsets/ends 1
__device__ int    g_cur2[N_TASK];           //  32 KB : counts/offsets/ends 2
__device__ int    g_srt1[NE1];              //   4 MB : src ids sorted by dst
__device__ int    g_srt2[NE2];              //   4 MB

// ---------------------------------------------------------------------------
// Generic small-N GEMM:  Y[row, 0:64] = act_out( act_in(X[row,:]) @ W + b )
// XSEL: 0 = external pointer, 1 = g_A.   YSEL: 0 = g_YG, 1 = g_A, 2 = g_X1.
// ---------------------------------------------------------------------------
template <int IN, bool ACT_IN, bool BIAS, bool RELU_OUT, int XSEL, int YSEL>
__global__ void __launch_bounds__(128) k_gemm(const float4* __restrict__ Xext,
                                              const float4* __restrict__ W,
                                              const float4* __restrict__ b)
{
    constexpr int KC  = 32;          // k-chunk
    constexpr int NCH = IN / KC;
    __shared__ float4 sW[KC * SDIM / 4];          //  8 KB
    __shared__ float4 sX[128 * (KC / 4 + 1)];     // 18.4 KB (pad 1 float4/row)

    const float4* X = (XSEL == 0) ? Xext : (const float4*)g_A;
    float4*       Y = (YSEL == 0) ? g_YG : (YSEL == 1) ? g_A : g_X1;

    const int tid  = threadIdx.x;
    const int row0 = blockIdx.x * 128;

    float4 acc[SDIM / 4];
#pragma unroll
    for (int k = 0; k < SDIM / 4; k++)
        acc[k] = BIAS ? b[k] : make_float4(0.f, 0.f, 0.f, 0.f);

    for (int ch = 0; ch < NCH; ch++) {
        __syncthreads();
#pragma unroll
        for (int i = 0; i < (KC * SDIM / 4) / 128; i++)
            sW[tid + i * 128] = W[ch * (KC * SDIM / 4) + tid + i * 128];
        {
            const float4* src = X + (size_t)row0 * (IN / 4) + ch * (KC / 4);
#pragma unroll
            for (int i = 0; i < KC / 4; i++) {
                int idx = tid + i * 128;
                int r = idx >> 3, c = idx & 7;
                float4 v = src[r * (IN / 4) + c];
                if (ACT_IN) {
                    v.x = fmaxf(v.x, 0.f); v.y = fmaxf(v.y, 0.f);
                    v.z = fmaxf(v.z, 0.f); v.w = fmaxf(v.w, 0.f);
                }
                sX[r * 9 + c] = v;
            }
        }
        __syncthreads();

        const float4* xrow = &sX[tid * 9];
#pragma unroll
        for (int f4 = 0; f4 < KC / 4; f4++) {
            float4 v = xrow[f4];
#pragma unroll
            for (int ff = 0; ff < 4; ff++) {
                float xf = (ff == 0) ? v.x : (ff == 1) ? v.y : (ff == 2) ? v.z : v.w;
                const float4* w = &sW[(f4 * 4 + ff) * (SDIM / 4)];
#pragma unroll
                for (int k = 0; k < SDIM / 4; k++) {
                    float4 wv = w[k];
                    acc[k].x += xf * wv.x;
                    acc[k].y += xf * wv.y;
                    acc[k].z += xf * wv.z;
                    acc[k].w += xf * wv.w;
                }
            }
        }
    }

    float4* yp = Y + (size_t)(row0 + tid) * (SDIM / 4);
#pragma unroll
    for (int k = 0; k < SDIM / 4; k++) {
        float4 a = acc[k];
        if (RELU_OUT) {
            a.x = fmaxf(a.x, 0.f); a.y = fmaxf(a.y, 0.f);
            a.z = fmaxf(a.z, 0.f); a.w = fmaxf(a.w, 0.f);
        }
        yp[k] = a;
    }
}

// ---------------------------------------------------------------------------
// counting sort by destination: zero -> hist -> scan -> place
// WHICH selects (g_cur1,g_srt1) or (g_cur2,g_srt2) from device code.
// ---------------------------------------------------------------------------
template <int WHICH>
__global__ void k_zero()
{
    int* cur = WHICH ? g_cur2 : g_cur1;
    cur[blockIdx.x * blockDim.x + threadIdx.x] = 0;
}

template <int WHICH>
__global__ void k_hist(const int* __restrict__ dst)
{
    int* cur = WHICH ? g_cur2 : g_cur1;
    int e = blockIdx.x * blockDim.x + threadIdx.x;
    atomicAdd(&cur[__ldg(&dst[e])], 1);
}

// single-block exclusive scan over N counts (N = 1024 * CH), in place.
template <int WHICH, int CH>
__global__ void __launch_bounds__(1024) k_scan()
{
    int* cur = WHICH ? g_cur2 : g_cur1;
    __shared__ int warpsum[32];
    const int tid  = threadIdx.x;
    const int base = tid * CH;

    int s = 0;
    for (int i = 0; i < CH; i++) s += cur[base + i];

    int lane = tid & 31, wid = tid >> 5;
    int v = s;
#pragma unroll
    for (int o = 1; o < 32; o <<= 1) {
        int t = __shfl_up_sync(~0u, v, o);
        if (lane >= o) v += t;
    }
    if (lane == 31) warpsum[wid] = v;
    __syncthreads();
    if (wid == 0) {
        int w = warpsum[lane];
#pragma unroll
        for (int o = 1; o < 32; o <<= 1) {
            int t = __shfl_up_sync(~0u, w, o);
            if (lane >= o) w += t;
        }
        warpsum[lane] = w;
    }
    __syncthreads();

    int run = v - s + (wid ? warpsum[wid - 1] : 0);   // exclusive base
    for (int i = 0; i < CH; i++) {
        int c = cur[base + i];
        cur[base + i] = run;
        run += c;
    }
}

template <int WHICH>
__global__ void k_place(const int* __restrict__ src,
                        const int* __restrict__ dst)
{
    int* cur = WHICH ? g_cur2 : g_cur1;
    int* srt = WHICH ? g_srt2 : g_srt1;
    int e = blockIdx.x * blockDim.x + threadIdx.x;
    int pos = atomicAdd(&cur[__ldg(&dst[e])], 1);
    srt[pos] = __ldg(&src[e]);
}
// after k_place: cur[d] == end offset of bin d; start = cur[d-1] (0 for d=0)

// ---------------------------------------------------------------------------
// gather 1: one warp per obs row; acc starts at g_A (= x_obs@W1 + b1),
// accumulates g_YG rows of all in-edges, single write back. Atomic-free.
// ---------------------------------------------------------------------------
__global__ void __launch_bounds__(256) k_gather1()
{
    const int lane = threadIdx.x & 31;
    const int d = blockIdx.x * 8 + (threadIdx.x >> 5);

    const int start = d ? __ldg(&g_cur1[d - 1]) : 0;
    const int end   = __ldg(&g_cur1[d]);

    float2*       A2 = (float2*)g_A;
    const float2* Y2 = (const float2*)g_YG;

    float2 acc = A2[d * 32 + lane];
    for (int b = start; b < end; b += 32) {
        int idx = b + lane;
        int sv = (idx < end) ? __ldg(&g_srt1[idx]) : 0;
        int n = min(32, end - b);
        for (int j = 0; j < n; j++) {
            int s = __shfl_sync(~0u, sv, j);
            float2 v = Y2[s * 32 + lane];
            acc.x += v.x; acc.y += v.y;
        }
    }
    A2[d * 32 + lane] = acc;
}

// ---------------------------------------------------------------------------
// gather 2: one warp per task row; acc starts at x_task, accumulates g_X1
// rows of in-edges, writes g_G.
// ---------------------------------------------------------------------------
__global__ void __launch_bounds__(256) k_gather2(const float2* __restrict__ x_task)
{
    const int lane = threadIdx.x & 31;
    const int d = blockIdx.x * 8 + (threadIdx.x >> 5);

    const int start = d ? __ldg(&g_cur2[d - 1]) : 0;
    const int end   = __ldg(&g_cur2[d]);

    const float2* X2 = (const float2*)g_X1;
    float2*       G2 = (float2*)g_G;

    float2 acc = x_task[d * 32 + lane];
    for (int b = start; b < end; b += 32) {
        int idx = b + lane;
        int sv = (idx < end) ? __ldg(&g_srt2[idx]) : 0;
        int n = min(32, end - b);
        for (int j = 0; j < n; j++) {
            int s = __shfl_sync(~0u, sv, j);
            float2 v = X2[s * 32 + lane];
            acc.x += v.x; acc.y += v.y;
        }
    }
    G2[d * 32 + lane] = acc;
}

// ---------------------------------------------------------------------------
// task MLP + per-graph pooling + critic head, fully fused.
// ---------------------------------------------------------------------------
__global__ void __launch_bounds__(256) k_task(const float* __restrict__ W3,
                                              const float* __restrict__ b3,
                                              const float* __restrict__ W4,
                                              const float* __restrict__ b4,
                                              const float* __restrict__ Wc1,
                                              const float* __restrict__ bc1,
                                              const float* __restrict__ Wc2,
                                              const float* __restrict__ bc2,
                                              float* __restrict__ out)
{
    __shared__ float sW[SDIM * SDIM];
    for (int i = threadIdx.x; i < SDIM * SDIM; i += 256) sW[i] = W3[i];
    __syncthreads();

    int node = blockIdx.x * 256 + threadIdx.x;   // == graph*32 + lane

    float4 acc[SDIM / 4];
    const float4* bv = (const float4*)b3;
#pragma unroll
    for (int k = 0; k < SDIM / 4; k++) acc[k] = bv[k];

    const float4* xp = g_G + node * (SDIM / 4);
    for (int f4 = 0; f4 < SDIM / 4; f4++) {
        float4 v = xp[f4];
#pragma unroll
        for (int ff = 0; ff < 4; ff++) {
            float xf = (ff == 0) ? v.x : (ff == 1) ? v.y : (ff == 2) ? v.z : v.w;
            const float4* w = (const float4*)&sW[(f4 * 4 + ff) * SDIM];
#pragma unroll
            for (int k = 0; k < SDIM / 4; k++) {
                float4 wv = w[k];
                acc[k].x += xf * wv.x;
                acc[k].y += xf * wv.y;
                acc[k].z += xf * wv.z;
                acc[k].w += xf * wv.w;
            }
        }
    }

    float x2 = b4[0];
    const float4* w4v = (const float4*)W4;
#pragma unroll
    for (int k = 0; k < SDIM / 4; k++) {
        float4 a = acc[k];
        float4 w = w4v[k];
        x2 += fmaxf(a.x, 0.f) * w.x + fmaxf(a.y, 0.f) * w.y +
              fmaxf(a.z, 0.f) * w.z + fmaxf(a.w, 0.f) * w.w;
    }

    float m = x2, s = x2;
#pragma unroll
    for (int o = 16; o; o >>= 1) {
        m = fmaxf(m, __shfl_xor_sync(0xFFFFFFFFu, m, o));
        s += __shfl_xor_sync(0xFFFFFFFFu, s, o);
    }

    if ((threadIdx.x & 31) == 0) {
        float mean = s * (1.0f / 32.0f);
        float o0 = bc2[0];
#pragma unroll
        for (int i = 0; i < 8; i++) {
            float hc = fmaxf(m * Wc1[i] + mean * Wc1[8 + i] + bc1[i], 0.f);
            o0 += hc * Wc2[i];
        }
        out[node >> 5] = o0;
    }
}

// ---------------------------------------------------------------------------
extern "C" void kernel_launch(void* const* d_in, const int* in_sizes, int n_in,
                              void* d_out, int out_size)
{
    const float4* x_goal = (const float4*)d_in[0];
    const float4* x_obs  = (const float4*)d_in[1];
    const float2* x_task = (const float2*)d_in[2];
    const int*    e1s    = (const int*)d_in[3];
    const int*    e1d    = (const int*)d_in[4];
    const int*    e2s    = (const int*)d_in[5];
    const int*    e2d    = (const int*)d_in[6];
    // d_in[7] = task_batch (contiguous 32/graph — hardcoded in k_task)
    const float4* W1  = (const float4*)d_in[8];
    const float4* b1  = (const float4*)d_in[9];
    const float4* W2  = (const float4*)d_in[10];
    const float4* b2  = (const float4*)d_in[11];
    const float*  W3  = (const float*)d_in[12];
    const float*  b3  = (const float*)d_in[13];
    const float*  W4  = (const float*)d_in[14];
    const float*  b4  = (const float*)d_in[15];
    const float*  Wc1 = (const float*)d_in[16];
    const float*  bc1 = (const float*)d_in[17];
    const float*  Wc2 = (const float*)d_in[18];
    const float*  bc2 = (const float*)d_in[19];
    float* out = (float*)d_out;

    // --- counting sorts (depend only on edge indices) ---
    k_zero<0><<<N_OBS / 256, 256>>>();
    k_hist<0><<<NE1 / 256, 256>>>(e1d);
    k_zero<1><<<N_TASK / 256, 256>>>();
    k_hist<1><<<NE2 / 256, 256>>>(e2d);
    k_scan<0, N_OBS / 1024><<<1, 1024>>>();
    k_place<0><<<NE1 / 256, 256>>>(e1s, e1d);
    k_scan<1, N_TASK / 1024><<<1, 1024>>>();
    k_place<1><<<NE2 / 256, 256>>>(e2s, e2d);

    // --- feature transforms ---
    // g_YG = x_goal @ W1  (push-through of W1)
    k_gemm<FDIM, false, false, false, 0, 0><<<N_GOAL / 128, 128>>>(x_goal, W1, b1);
    // g_A  = x_obs @ W1 + b1
    k_gemm<FDIM, false, true,  false, 0, 1><<<N_OBS  / 128, 128>>>(x_obs,  W1, b1);

    // g_A += sum over in-edges of g_YG rows (atomic-free binned gather)
    k_gather1<<<N_OBS / 8, 256>>>();

    // g_X1 = relu( relu(g_A) @ W2 + b2 )
    k_gemm<SDIM, true, true, true, 1, 2><<<N_OBS / 128, 128>>>(nullptr, W2, b2);

    // g_G = x_task + sum over in-edges of g_X1 rows
    k_gather2<<<N_TASK / 8, 256>>>(x_task);

    k_task<<<N_TASK / 256, 256>>>(W3, b3, W4, b4, Wc1, bc1, Wc2, bc2, out);
}

// round 6
// speedup vs baseline: 1.5774x; 1.5774x over previous
#include <cuda_runtime.h>

#define N_GOAL 16384
#define N_OBS  65536
#define N_TASK 8192
#define NE1    1048576
#define NE2    1048576
#define NB     256
#define FDIM   128
#define SDIM   64

// Scratch (static __device__ arrays — referenced from DEVICE code only!).
__device__ float4 g_YG[N_GOAL * SDIM / 4];  //  4 MB : x_goal @ W1
__device__ float4 g_A [N_OBS  * SDIM / 4];  // 16 MB : x_obs@W1 + b1 + agg
__device__ float4 g_X1[N_OBS  * SDIM / 4];  // 16 MB : after layer 2
__device__ float4 g_G [N_TASK * SDIM / 4];  //  2 MB : x_task + agg2

// ---- packed f32x2 helpers (B300: doubles fp32 FMA rate; PTX-only) ---------
__device__ __forceinline__ unsigned long long f2fma(unsigned long long a,
                                                    unsigned long long b,
                                                    unsigned long long c)
{
    unsigned long long d;
    asm("fma.rn.f32x2 %0, %1, %2, %3;" : "=l"(d) : "l"(a), "l"(b), "l"(c));
    return d;
}
__device__ __forceinline__ unsigned long long f2dup(float x)
{
    unsigned long long d;
    asm("mov.b64 %0, {%1, %1};" : "=l"(d) : "f"(x));
    return d;
}
__device__ __forceinline__ float2 f2unpk(unsigned long long a)
{
    float2 f;
    asm("mov.b64 {%0, %1}, %2;" : "=f"(f.x), "=f"(f.y) : "l"(a));
    return f;
}

// ---------------------------------------------------------------------------
// Generic small-N GEMM:  Y[row, 0:64] = act_out( act_in(X[row,:]) @ W + b )
// 128 threads / 128 rows per block; X and W staged through SMEM in K-chunks.
// Inner product done with packed fma.rn.f32x2 (32 pairs per row).
// XSEL: 0 = external pointer, 1 = g_A.   YSEL: 0 = g_YG, 1 = g_A, 2 = g_X1.
// ---------------------------------------------------------------------------
template <int IN, bool ACT_IN, bool BIAS, bool RELU_OUT, int XSEL, int YSEL>
__global__ void __launch_bounds__(128) k_gemm(const float4* __restrict__ Xext,
                                              const float4* __restrict__ W,
                                              const float4* __restrict__ b)
{
    constexpr int KC  = 32;          // k-chunk
    constexpr int NCH = IN / KC;
    __shared__ float4 sW[KC * SDIM / 4];          //  8 KB
    __shared__ float4 sX[128 * (KC / 4 + 1)];     // 18.4 KB (pad 1 float4/row)

    const float4* X = (XSEL == 0) ? Xext : (const float4*)g_A;
    float4*       Y = (YSEL == 0) ? g_YG : (YSEL == 1) ? g_A : g_X1;

    const int tid  = threadIdx.x;
    const int row0 = blockIdx.x * 128;

    unsigned long long acc[SDIM / 2];            // 32 packed pairs = 64 floats
    if (BIAS) {
        const double* bd = (const double*)b;
#pragma unroll
        for (int k = 0; k < SDIM / 2; k++)
            acc[k] = __double_as_longlong(bd[k]);
    } else {
#pragma unroll
        for (int k = 0; k < SDIM / 2; k++) acc[k] = 0ull;   // (0.f, 0.f)
    }

    for (int ch = 0; ch < NCH; ch++) {
        __syncthreads();
#pragma unroll
        for (int i = 0; i < (KC * SDIM / 4) / 128; i++)
            sW[tid + i * 128] = W[ch * (KC * SDIM / 4) + tid + i * 128];
        {
            const float4* src = X + (size_t)row0 * (IN / 4) + ch * (KC / 4);
#pragma unroll
            for (int i = 0; i < KC / 4; i++) {
                int idx = tid + i * 128;
                int r = idx >> 3, c = idx & 7;
                float4 v = src[r * (IN / 4) + c];
                if (ACT_IN) {
                    v.x = fmaxf(v.x, 0.f); v.y = fmaxf(v.y, 0.f);
                    v.z = fmaxf(v.z, 0.f); v.w = fmaxf(v.w, 0.f);
                }
                sX[r * 9 + c] = v;
            }
        }
        __syncthreads();

        const float4* xrow = &sX[tid * 9];
#pragma unroll
        for (int f4 = 0; f4 < KC / 4; f4++) {
            float4 v = xrow[f4];
#pragma unroll
            for (int ff = 0; ff < 4; ff++) {
                float xf = (ff == 0) ? v.x : (ff == 1) ? v.y : (ff == 2) ? v.z : v.w;
                unsigned long long x2 = f2dup(xf);
                // W row for this k: 64 floats = 16 double2 (LDS.128, broadcast)
                const double2* w = (const double2*)&sW[(f4 * 4 + ff) * (SDIM / 4)];
#pragma unroll
                for (int k = 0; k < SDIM / 4; k++) {
                    double2 wd = w[k];
                    acc[2 * k]     = f2fma(__double_as_longlong(wd.x), x2, acc[2 * k]);
                    acc[2 * k + 1] = f2fma(__double_as_longlong(wd.y), x2, acc[2 * k + 1]);
                }
            }
        }
    }

    float4* yp = Y + (size_t)(row0 + tid) * (SDIM / 4);
#pragma unroll
    for (int k = 0; k < SDIM / 4; k++) {
        float2 lo = f2unpk(acc[2 * k]);
        float2 hi = f2unpk(acc[2 * k + 1]);
        float4 a = make_float4(lo.x, lo.y, hi.x, hi.y);
        if (RELU_OUT) {
            a.x = fmaxf(a.x, 0.f); a.y = fmaxf(a.y, 0.f);
            a.z = fmaxf(a.z, 0.f); a.w = fmaxf(a.w, 0.f);
        }
        yp[k] = a;
    }
}

// ---------------------------------------------------------------------------
// init: g_G = x_task
// ---------------------------------------------------------------------------
__global__ void k_init2(const float4* __restrict__ x_task)
{
    int i = blockIdx.x * blockDim.x + threadIdx.x;
    g_G[i] = x_task[i];
}

// ---------------------------------------------------------------------------
// scatter 1 (post-W1): 16 lanes per edge, 64-float rows of g_YG into g_A.
// ---------------------------------------------------------------------------
__global__ void k_scatter1(const int* __restrict__ src,
                           const int* __restrict__ dst)
{
    int tid = blockIdx.x * blockDim.x + threadIdx.x;
    int e = tid >> 4;
    int c = tid & 15;
    int s = __ldg(&src[e]);
    int d = __ldg(&dst[e]);
    float4 v = g_YG[s * (SDIM / 4) + c];
    atomicAdd(&g_A[d * (SDIM / 4) + c], v);   // red.global.v4.f32
}

// ---------------------------------------------------------------------------
// scatter 2: 16 lanes per edge (x1 rows into g_G).
// ---------------------------------------------------------------------------
__global__ void k_scatter2(const int* __restrict__ src,
                           const int* __restrict__ dst)
{
    int tid = blockIdx.x * blockDim.x + threadIdx.x;
    int e = tid >> 4;
    int c = tid & 15;
    int s = __ldg(&src[e]);
    int d = __ldg(&dst[e]);
    float4 v = g_X1[s * (SDIM / 4) + c];
    atomicAdd(&g_G[d * (SDIM / 4) + c], v);
}

// ---------------------------------------------------------------------------
// task MLP + per-graph pooling + critic head, fully fused.
// One thread per task node; one warp per graph (32 contiguous nodes/graph).
// ---------------------------------------------------------------------------
__global__ void __launch_bounds__(256) k_task(const float* __restrict__ W3,
                                              const float* __restrict__ b3,
                                              const float* __restrict__ W4,
                                              const float* __restrict__ b4,
                                              const float* __restrict__ Wc1,
                                              const float* __restrict__ bc1,
                                              const float* __restrict__ Wc2,
                                              const float* __restrict__ bc2,
                                              float* __restrict__ out)
{
    __shared__ float sW[SDIM * SDIM];
    for (int i = threadIdx.x; i < SDIM * SDIM; i += 256) sW[i] = W3[i];
    __syncthreads();

    int node = blockIdx.x * 256 + threadIdx.x;   // == graph*32 + lane

    float4 acc[SDIM / 4];
    const float4* bv = (const float4*)b3;
#pragma unroll
    for (int k = 0; k < SDIM / 4; k++) acc[k] = bv[k];

    const float4* xp = g_G + node * (SDIM / 4);
    for (int f4 = 0; f4 < SDIM / 4; f4++) {
        float4 v = xp[f4];
#pragma unroll
        for (int ff = 0; ff < 4; ff++) {
            float xf = (ff == 0) ? v.x : (ff == 1) ? v.y : (ff == 2) ? v.z : v.w;
            const float4* w = (const float4*)&sW[(f4 * 4 + ff) * SDIM];
#pragma unroll
            for (int k = 0; k < SDIM / 4; k++) {
                float4 wv = w[k];
                acc[k].x += xf * wv.x;
                acc[k].y += xf * wv.y;
                acc[k].z += xf * wv.z;
                acc[k].w += xf * wv.w;
            }
        }
    }

    // x2 = relu(g) . W4 + b4
    float x2 = b4[0];
    const float4* w4v = (const float4*)W4;
#pragma unroll
    for (int k = 0; k < SDIM / 4; k++) {
        float4 a = acc[k];
        float4 w = w4v[k];
        x2 += fmaxf(a.x, 0.f) * w.x + fmaxf(a.y, 0.f) * w.y +
              fmaxf(a.z, 0.f) * w.z + fmaxf(a.w, 0.f) * w.w;
    }

    // warp = one graph: max & sum over 32 task nodes
    float m = x2, s = x2;
#pragma unroll
    for (int o = 16; o; o >>= 1) {
        m = fmaxf(m, __shfl_xor_sync(0xFFFFFFFFu, m, o));
        s += __shfl_xor_sync(0xFFFFFFFFu, s, o);
    }

    if ((threadIdx.x & 31) == 0) {
        float mean = s * (1.0f / 32.0f);
        float o0 = bc2[0];
#pragma unroll
        for (int i = 0; i < 8; i++) {
            float hc = fmaxf(m * Wc1[i] + mean * Wc1[8 + i] + bc1[i], 0.f);
            o0 += hc * Wc2[i];
        }
        out[node >> 5] = o0;
    }
}

// ---------------------------------------------------------------------------
extern "C" void kernel_launch(void* const* d_in, const int* in_sizes, int n_in,
                              void* d_out, int out_size)
{
    const float4* x_goal = (const float4*)d_in[0];
    const float4* x_obs  = (const float4*)d_in[1];
    const float4* x_task = (const float4*)d_in[2];
    const int*    e1s    = (const int*)d_in[3];
    const int*    e1d    = (const int*)d_in[4];
    const int*    e2s    = (const int*)d_in[5];
    const int*    e2d    = (const int*)d_in[6];
    // d_in[7] = task_batch (contiguous 32/graph — hardcoded in k_task)
    const float4* W1  = (const float4*)d_in[8];
    const float4* b1  = (const float4*)d_in[9];
    const float4* W2  = (const float4*)d_in[10];
    const float4* b2  = (const float4*)d_in[11];
    const float*  W3  = (const float*)d_in[12];
    const float*  b3  = (const float*)d_in[13];
    const float*  W4  = (const float*)d_in[14];
    const float*  b4  = (const float*)d_in[15];
    const float*  Wc1 = (const float*)d_in[16];
    const float*  bc1 = (const float*)d_in[17];
    const float*  Wc2 = (const float*)d_in[18];
    const float*  bc2 = (const float*)d_in[19];
    float* out = (float*)d_out;

    // g_YG = x_goal @ W1            (algebraic push-through of W1)
    k_gemm<FDIM, false, false, false, 0, 0><<<N_GOAL / 128, 128>>>(x_goal, W1, b1);
    // g_A  = x_obs @ W1 + b1        (accumulator base; atomics add on top)
    k_gemm<FDIM, false, true,  false, 0, 1><<<N_OBS  / 128, 128>>>(x_obs,  W1, b1);
    // g_G  = x_task
    k_init2<<<N_TASK * SDIM / 4 / 256, 256>>>(x_task);

    // g_A += sum_j g_YG[src_j]  over edges (64-float rows)
    k_scatter1<<<NE1 * 16 / 256, 256>>>(e1s, e1d);

    // g_X1 = relu( relu(g_A) @ W2 + b2 )
    k_gemm<SDIM, true, true, true, 1, 2><<<N_OBS / 128, 128>>>(nullptr, W2, b2);

    // g_G += sum_j g_X1[src_j]
    k_scatter2<<<NE2 * 16 / 256, 256>>>(e2s, e2d);

    k_task<<<N_TASK / 256, 256>>>(W3, b3, W4, b4, Wc1, bc1, Wc2, bc2, out);
}